// round 5
// baseline (speedup 1.0000x reference)
#include <cuda_runtime.h>
#include <cuda_bf16.h>
#include <math.h>
#include <stdint.h>

#define Bn   8
#define Cc   256
#define C2   512
#define Hh   128
#define Ww   128
#define HW   16384
#define BHW  131072
#define HID  64

// Scratch (device globals: allocation-free rule)
__device__ float g_off[(size_t)BHW * 4];      // per-pixel (dx_rgb, dy_rgb, dx_tir, dy_tir), pre-scaled
__device__ float g_p1wT[C2 * HID];            // p1 weights transposed [c][h]
__device__ float g_p2eff[HID * 4];            // folded p2
__device__ float g_p2beff[4];
__device__ float g_pooled[Bn * C2];
__device__ float g_mod[Bn * Cc];

// ---- packed fp32x2 helpers ----
__device__ __forceinline__ void fma2(unsigned long long& d, unsigned long long a, unsigned long long b) {
    asm("fma.rn.f32x2 %0, %1, %2, %0;" : "+l"(d) : "l"(a), "l"(b));
}
__device__ __forceinline__ unsigned long long pk2(float x) {
    unsigned long long r;
    asm("mov.b64 %0, {%1, %1};" : "=l"(r) : "f"(x));
    return r;
}
__device__ __forceinline__ void upk2(float& lo, float& hi, unsigned long long v) {
    asm("mov.b64 {%0, %1}, %2;" : "=f"(lo), "=f"(hi) : "l"(v));
}
// ---- cp.async helpers ----
__device__ __forceinline__ uint32_t smem_u32(const void* p) {
    return (uint32_t)__cvta_generic_to_shared(p);
}
__device__ __forceinline__ void cpa4(uint32_t dst, const float* src, int sz) {
    asm volatile("cp.async.ca.shared.global [%0], [%1], 4, %2;" :: "r"(dst), "l"(src), "r"(sz));
}
__device__ __forceinline__ void cpa_commit() { asm volatile("cp.async.commit_group;"); }
__device__ __forceinline__ void cpa_wait1() { asm volatile("cp.async.wait_group 1;"); }

// ---------------- prep: transpose p1, fold p2 ----------------
__global__ void prep_kernel(const float* __restrict__ p1w,
                            const float* __restrict__ p2w,
                            const float* __restrict__ p2b) {
    int idx = blockIdx.x * 256 + threadIdx.x;
    if (idx < C2 * HID) {
        int h = idx >> 9, c = idx & 511;   // p1w is [64][512] row-major
        g_p1wT[c * HID + h] = p1w[idx];
    }
    if (blockIdx.x == 0) {
        const float SC = 0.1f * 0.5f * 127.0f * 0.25f;
        if (threadIdx.x < HID) {
            int h = threadIdx.x;
            g_p2eff[h*4+0] = SC*(p2w[0*HID+h]+p2w[2*HID+h]+p2w[4*HID+h]+p2w[6*HID+h]);
            g_p2eff[h*4+1] = SC*(p2w[1*HID+h]+p2w[3*HID+h]+p2w[5*HID+h]+p2w[7*HID+h]);
            g_p2eff[h*4+2] = SC*(p2w[8*HID+h]+p2w[10*HID+h]+p2w[12*HID+h]+p2w[14*HID+h]);
            g_p2eff[h*4+3] = SC*(p2w[9*HID+h]+p2w[11*HID+h]+p2w[13*HID+h]+p2w[15*HID+h]);
        } else if (threadIdx.x < HID + 4) {
            int j = threadIdx.x - HID;
            int base = (j >> 1) * 8 + (j & 1);  // 0,1,8,9
            g_p2beff[j] = SC*(p2b[base]+p2b[base+2]+p2b[base+4]+p2b[base+6]);
        }
    }
}

// ---------------- GAP ----------------
__global__ void gap_kernel(const float* __restrict__ rgb, const float* __restrict__ tir) {
    int bc = blockIdx.x;               // 0..4095
    int b = bc >> 9, c2 = bc & 511;
    const float* src = (c2 < Cc) ? rgb + (size_t)(b * Cc + c2) * HW
                                 : tir + (size_t)(b * Cc + c2 - Cc) * HW;
    float s = 0.f;
    for (int i = threadIdx.x; i < HW; i += 256) s += src[i];
    __shared__ float sm[8];
    #pragma unroll
    for (int o = 16; o; o >>= 1) s += __shfl_xor_sync(0xffffffffu, s, o);
    if ((threadIdx.x & 31) == 0) sm[threadIdx.x >> 5] = s;
    __syncthreads();
    if (threadIdx.x < 8) {
        float v = sm[threadIdx.x];
        #pragma unroll
        for (int o = 4; o; o >>= 1) v += __shfl_xor_sync(0xffu, v, o);
        if (threadIdx.x == 0) g_pooled[bc] = v * (1.0f / (float)HW);
    }
}

// ---------------- modulation ----------------
__global__ void mod_kernel(const float* __restrict__ m1w, const float* __restrict__ m1b,
                           const float* __restrict__ m2w, const float* __restrict__ m2b) {
    int b = blockIdx.x;
    __shared__ float hid[HID];
    __shared__ float pl[C2];
    for (int i = threadIdx.x; i < C2; i += 256) pl[i] = g_pooled[b * C2 + i];
    __syncthreads();
    if (threadIdx.x < HID) {
        float s = m1b[threadIdx.x];
        const float* wr = m1w + threadIdx.x * C2;
        for (int c = 0; c < C2; c++) s = fmaf(wr[c], pl[c], s);
        hid[threadIdx.x] = fmaxf(s, 0.f);
    }
    __syncthreads();
    int o = threadIdx.x;
    float s = m2b[o];
    const float* wr = m2w + o * HID;
    #pragma unroll
    for (int h = 0; h < HID; h++) s = fmaf(wr[h], hid[h], s);
    g_mod[b * Cc + o] = 1.f / (1.f + expf(-s));
}

// ---------------- FUSED: depthwise 3x3 + p1 GEMM(+ReLU) + folded p2 ----------------
// Thread = 1 pixel, all 64 hid (32 f32x2 accs). Triple-buffered smem, 1 barrier/chunk.
#define TW 32
#define TH 8
#define HALO 340   // 10*34
#define CHK 8
#define NCHUNK (C2 / CHK)
#define NSLOT 11   // ceil(CHK*HALO / 256)

struct __align__(16) SmemT {
    float tiles[3][CHK * HALO];     // 3 x 10880 B
    float wch[3][CHK * HID];        // 3 x 2048 B
    float wdw[3][CHK * 12];         // 3 x 384 B  (9 taps + bias + 2 pad, float4-aligned rows)
};

__global__ __launch_bounds__(256, 2)
void dwgemm_kernel(const float* __restrict__ rgb, const float* __restrict__ tir,
                   const float* __restrict__ dww, const float* __restrict__ dwb,
                   const float* __restrict__ p1b) {
    __shared__ SmemT s;

    const int tid = threadIdx.x;
    const int tx0 = blockIdx.x * TW;
    const int ty0 = blockIdx.y * TH;
    const int b   = blockIdx.z;
    const int lx = tid & 31, ly = tid >> 5;

    // ---- precompute loader slot addressing (chunk-invariant) ----
    int ofs[NSLOT];            // ch*HW + (valid ? gy*Ww+gx : 0)
    unsigned vmask = 0;
    #pragma unroll
    for (int sl = 0; sl < NSLOT; sl++) {
        int i = sl * 256 + tid;
        int ch = i / HALO;
        int rem = i - ch * HALO;
        int r = rem / 34, col = rem - r * 34;
        int gy = ty0 + r - 1, gx = tx0 + col - 1;
        bool have = (i < CHK * HALO);
        bool in = have && ((unsigned)gy < (unsigned)Hh) && ((unsigned)gx < (unsigned)Ww);
        ofs[sl] = (have ? ch * HW : 0) + (in ? gy * Ww + gx : 0);
        if (in) vmask |= 1u << sl;
    }

    const float* rbase = rgb + (size_t)b * Cc * HW;
    const float* tbase = tir + (size_t)b * Cc * HW;
    const uint32_t tiles_a = smem_u32(s.tiles);
    const uint32_t wch_a   = smem_u32(s.wch);
    const uint32_t wdw_a   = smem_u32(s.wdw);

    auto load_chunk = [&](int chunk, int bt) {
        const float* base = (chunk < 32 ? rbase : tbase) + (size_t)((chunk & 31) * CHK) * HW;
        uint32_t dst0 = tiles_a + (bt * (CHK * HALO) + tid) * 4;
        #pragma unroll
        for (int sl = 0; sl < NSLOT; sl++) {
            if (sl < NSLOT - 1 || tid < (CHK * HALO - (NSLOT - 1) * 256)) {
                int in = (vmask >> sl) & 1;
                cpa4(dst0 + sl * 256 * 4, base + ofs[sl], in ? 4 : 0);
            }
        }
        cpa4(wch_a + (bt * (CHK * HID) + tid) * 4,       g_p1wT + chunk * (CHK * HID) + tid, 4);
        cpa4(wch_a + (bt * (CHK * HID) + tid + 256) * 4, g_p1wT + chunk * (CHK * HID) + tid + 256, 4);
        if (tid < CHK * 12) {
            int cc = tid / 12, k = tid - cc * 12;
            const float* src = (k < 9) ? dww + (chunk * CHK + cc) * 9 + k
                                       : dwb + chunk * CHK + cc;
            cpa4(wdw_a + (bt * (CHK * 12) + tid) * 4, src, (k <= 9) ? 4 : 0);
        }
    };

    unsigned long long acc[32];
    #pragma unroll
    for (int i = 0; i < 32; i++) acc[i] = 0ULL;

    load_chunk(0, 0);
    cpa_commit();

    for (int chunk = 0; chunk < NCHUNK; chunk++) {
        const int bt = chunk % 3;
        if (chunk + 1 < NCHUNK) load_chunk(chunk + 1, (chunk + 1) % 3);
        cpa_commit();
        cpa_wait1();
        __syncthreads();

        // ---- Stage B: depthwise for my pixel -> x[8] registers ----
        float x[CHK];
        const float* t0 = &s.tiles[bt][ly * 34 + lx];
        const float* wd = &s.wdw[bt][0];
        #pragma unroll
        for (int cc = 0; cc < CHK; cc++) {
            const float* t = t0 + cc * HALO;
            float4 wa = *(const float4*)(wd + cc * 12);
            float4 wb = *(const float4*)(wd + cc * 12 + 4);
            float2 wc = *(const float2*)(wd + cc * 12 + 8);
            float o = wc.y;   // bias
            o = fmaf(wa.x, t[0],  fmaf(wa.y, t[1],  fmaf(wa.z, t[2],
                fmaf(wa.w, t[34], fmaf(wb.x, t[35], fmaf(wb.y, t[36],
                fmaf(wb.z, t[68], fmaf(wb.w, t[69], fmaf(wc.x, t[70], o)))))))));
            x[cc] = o;
        }

        // ---- Stage C: GEMM accumulate (weights broadcast across warp) ----
        #pragma unroll
        for (int cc = 0; cc < CHK; cc++) {
            unsigned long long xx = pk2(x[cc]);
            const ulonglong2* wp = (const ulonglong2*)&s.wch[bt][cc * HID];
            #pragma unroll
            for (int q = 0; q < 16; q++) {
                ulonglong2 w2 = wp[q];
                fma2(acc[2 * q],     w2.x, xx);
                fma2(acc[2 * q + 1], w2.y, xx);
            }
        }
        // next iteration's barrier protects slot reuse (writer is 2 slots ahead)
    }

    // ---- Epilogue: per-thread bias + ReLU + folded p2 ----
    float4 o = make_float4(g_p2beff[0], g_p2beff[1], g_p2beff[2], g_p2beff[3]);
    #pragma unroll
    for (int p = 0; p < 32; p++) {
        float h0, h1;
        upk2(h0, h1, acc[p]);
        float2 bb = *(const float2*)(p1b + 2 * p);
        h0 = fmaxf(h0 + bb.x, 0.f);
        h1 = fmaxf(h1 + bb.y, 0.f);
        float4 e0 = *(const float4*)(g_p2eff + (2 * p) * 4);
        float4 e1 = *(const float4*)(g_p2eff + (2 * p + 1) * 4);
        o.x += e0.x * h0 + e1.x * h1;
        o.y += e0.y * h0 + e1.y * h1;
        o.z += e0.z * h0 + e1.z * h1;
        o.w += e0.w * h0 + e1.w * h1;
    }
    int py = ty0 + ly, px = tx0 + lx;
    ((float4*)g_off)[b * HW + py * Ww + px] = o;
}

// ---------------- bilinear sample + mod + quality ----------------
__global__ void sample_kernel(const float* __restrict__ rgb, const float* __restrict__ tir,
                              float* __restrict__ out) {
    int x = threadIdx.x;        // 128
    int y = blockIdx.x;         // 128
    int b = blockIdx.y;         // 8
    __shared__ float smod[Cc];
    for (int i = threadIdx.x; i < Cc; i += 128) smod[i] = g_mod[b * Cc + i];
    __syncthreads();
    int hw = y * Ww + x;
    int p = b * HW + hw;
    float4 off = ((const float4*)g_off)[p];

    float ixr = fminf(fmaxf((float)x + off.x, 0.f), 127.f);
    float iyr = fminf(fmaxf((float)y + off.y, 0.f), 127.f);
    float ixt = fminf(fmaxf((float)x + off.z, 0.f), 127.f);
    float iyt = fminf(fmaxf((float)y + off.w, 0.f), 127.f);

    float fx0r = floorf(ixr), fy0r = floorf(iyr);
    int x0r = (int)fx0r, y0r = (int)fy0r;
    int x1r = min(x0r + 1, 127), y1r = min(y0r + 1, 127);
    float wxr = ixr - fx0r, wyr = iyr - fy0r;
    int i00r = y0r*Ww + x0r, i01r = y0r*Ww + x1r, i10r = y1r*Ww + x0r, i11r = y1r*Ww + x1r;

    float fx0t = floorf(ixt), fy0t = floorf(iyt);
    int x0t = (int)fx0t, y0t = (int)fy0t;
    int x1t = min(x0t + 1, 127), y1t = min(y0t + 1, 127);
    float wxt = ixt - fx0t, wyt = iyt - fy0t;
    int i00t = y0t*Ww + x0t, i01t = y0t*Ww + x1t, i10t = y1t*Ww + x0t, i11t = y1t*Ww + x1t;

    const float* rb = rgb + (size_t)b * Cc * HW;
    const float* tb = tir + (size_t)b * Cc * HW;
    float* outR = out + (size_t)b * Cc * HW + hw;
    float* outT = out + (size_t)Bn * Cc * HW + (size_t)b * Cc * HW + hw;

    float qacc = 0.f;
    #pragma unroll 4
    for (int c = 0; c < Cc; c++) {
        size_t co = (size_t)c * HW;
        float v00 = rb[co + i00r], v01 = rb[co + i01r];
        float v10 = rb[co + i10r], v11 = rb[co + i11r];
        float topr = v00 * (1.f - wxr) + v01 * wxr;
        float botr = v10 * (1.f - wxr) + v11 * wxr;
        float rv = (topr * (1.f - wyr) + botr * wyr) * smod[c];

        float u00 = tb[co + i00t], u01 = tb[co + i01t];
        float u10 = tb[co + i10t], u11 = tb[co + i11t];
        float topt = u00 * (1.f - wxt) + u01 * wxt;
        float bott = u10 * (1.f - wxt) + u11 * wxt;
        float tv = (topt * (1.f - wyt) + bott * wyt) * smod[c];

        outR[co] = rv;
        outT[co] = tv;
        qacc += fabsf(rv - tv);
    }
    float q = 1.f - qacc * (1.f / (float)Cc);
    out[(size_t)2 * Bn * Cc * HW + p] = 1.f / (1.f + expf(-q));
}

extern "C" void kernel_launch(void* const* d_in, const int* in_sizes, int n_in,
                              void* d_out, int out_size) {
    const float* rgb  = (const float*)d_in[0];
    const float* tir  = (const float*)d_in[1];
    const float* dw_w = (const float*)d_in[2];
    const float* dw_b = (const float*)d_in[3];
    const float* p1_w = (const float*)d_in[4];
    const float* p1_b = (const float*)d_in[5];
    const float* p2_w = (const float*)d_in[6];
    const float* p2_b = (const float*)d_in[7];
    const float* m1_w = (const float*)d_in[8];
    const float* m1_b = (const float*)d_in[9];
    const float* m2_w = (const float*)d_in[10];
    const float* m2_b = (const float*)d_in[11];
    float* out = (float*)d_out;

    prep_kernel<<<129, 256>>>(p1_w, p2_w, p2_b);
    gap_kernel<<<Bn * C2, 256>>>(rgb, tir);
    mod_kernel<<<Bn, 256>>>(m1_w, m1_b, m2_w, m2_b);
    dwgemm_kernel<<<dim3(Ww / TW, Hh / TH, Bn), 256>>>(rgb, tir, dw_w, dw_b, p1_b);
    sample_kernel<<<dim3(Hh, Bn), Ww>>>(rgb, tir, out);
}

// round 7
// speedup vs baseline: 1.2088x; 1.2088x over previous
#include <cuda_runtime.h>
#include <cuda_bf16.h>
#include <math.h>
#include <stdint.h>

#define Bn   8
#define Cc   256
#define C2   512
#define Hh   128
#define Ww   128
#define HW   16384
#define BHW  131072
#define HID  64

// Scratch (device globals: allocation-free rule)
__device__ float g_off[(size_t)BHW * 4];
__device__ float g_p1wT[C2 * HID];
__device__ float g_p2eff[HID * 4];
__device__ float g_p2beff[4];
__device__ float g_pooled[Bn * C2];
__device__ float g_mod[Bn * Cc];

// ---- packed fp32x2 helpers ----
__device__ __forceinline__ void fma2(unsigned long long& d, unsigned long long a, unsigned long long b) {
    asm("fma.rn.f32x2 %0, %1, %2, %0;" : "+l"(d) : "l"(a), "l"(b));
}
__device__ __forceinline__ unsigned long long pk2(float x) {
    unsigned long long r;
    asm("mov.b64 %0, {%1, %1};" : "=l"(r) : "f"(x));
    return r;
}
__device__ __forceinline__ void upk2(float& lo, float& hi, unsigned long long v) {
    asm("mov.b64 {%0, %1}, %2;" : "=f"(lo), "=f"(hi) : "l"(v));
}
// ---- cp.async helpers ----
__device__ __forceinline__ uint32_t smem_u32(const void* p) {
    return (uint32_t)__cvta_generic_to_shared(p);
}
__device__ __forceinline__ void cpa4(uint32_t dst, const float* src, int sz) {
    asm volatile("cp.async.ca.shared.global [%0], [%1], 4, %2;" :: "r"(dst), "l"(src), "r"(sz));
}
__device__ __forceinline__ void cpa_commit() { asm volatile("cp.async.commit_group;"); }
__device__ __forceinline__ void cpa_wait1() { asm volatile("cp.async.wait_group 1;"); }
__device__ __forceinline__ void cpa_wait0() { asm volatile("cp.async.wait_group 0;"); }

// ---------------- prep: transpose p1, fold p2 ----------------
__global__ void prep_kernel(const float* __restrict__ p1w,
                            const float* __restrict__ p2w,
                            const float* __restrict__ p2b) {
    int idx = blockIdx.x * 256 + threadIdx.x;
    if (idx < C2 * HID) {
        int h = idx >> 9, c = idx & 511;   // p1w is [64][512] row-major
        g_p1wT[c * HID + h] = p1w[idx];
    }
    if (blockIdx.x == 0) {
        const float SC = 0.1f * 0.5f * 127.0f * 0.25f;
        if (threadIdx.x < HID) {
            int h = threadIdx.x;
            g_p2eff[h*4+0] = SC*(p2w[0*HID+h]+p2w[2*HID+h]+p2w[4*HID+h]+p2w[6*HID+h]);
            g_p2eff[h*4+1] = SC*(p2w[1*HID+h]+p2w[3*HID+h]+p2w[5*HID+h]+p2w[7*HID+h]);
            g_p2eff[h*4+2] = SC*(p2w[8*HID+h]+p2w[10*HID+h]+p2w[12*HID+h]+p2w[14*HID+h]);
            g_p2eff[h*4+3] = SC*(p2w[9*HID+h]+p2w[11*HID+h]+p2w[13*HID+h]+p2w[15*HID+h]);
        } else if (threadIdx.x < HID + 4) {
            int j = threadIdx.x - HID;
            int base = (j >> 1) * 8 + (j & 1);  // 0,1,8,9
            g_p2beff[j] = SC*(p2b[base]+p2b[base+2]+p2b[base+4]+p2b[base+6]);
        }
    }
}

// ---------------- GAP ----------------
__global__ void gap_kernel(const float* __restrict__ rgb, const float* __restrict__ tir) {
    int bc = blockIdx.x;               // 0..4095
    int b = bc >> 9, c2 = bc & 511;
    const float* src = (c2 < Cc) ? rgb + (size_t)(b * Cc + c2) * HW
                                 : tir + (size_t)(b * Cc + c2 - Cc) * HW;
    float s = 0.f;
    for (int i = threadIdx.x; i < HW; i += 256) s += src[i];
    __shared__ float sm[8];
    #pragma unroll
    for (int o = 16; o; o >>= 1) s += __shfl_xor_sync(0xffffffffu, s, o);
    if ((threadIdx.x & 31) == 0) sm[threadIdx.x >> 5] = s;
    __syncthreads();
    if (threadIdx.x < 8) {
        float v = sm[threadIdx.x];
        #pragma unroll
        for (int o = 4; o; o >>= 1) v += __shfl_xor_sync(0xffu, v, o);
        if (threadIdx.x == 0) g_pooled[bc] = v * (1.0f / (float)HW);
    }
}

// ---------------- modulation ----------------
__global__ void mod_kernel(const float* __restrict__ m1w, const float* __restrict__ m1b,
                           const float* __restrict__ m2w, const float* __restrict__ m2b) {
    int b = blockIdx.x;
    __shared__ float hid[HID];
    __shared__ float pl[C2];
    for (int i = threadIdx.x; i < C2; i += 256) pl[i] = g_pooled[b * C2 + i];
    __syncthreads();
    if (threadIdx.x < HID) {
        float s = m1b[threadIdx.x];
        const float* wr = m1w + threadIdx.x * C2;
        for (int c = 0; c < C2; c++) s = fmaf(wr[c], pl[c], s);
        hid[threadIdx.x] = fmaxf(s, 0.f);
    }
    __syncthreads();
    int o = threadIdx.x;
    float s = m2b[o];
    const float* wr = m2w + o * HID;
    #pragma unroll
    for (int h = 0; h < HID; h++) s = fmaf(wr[h], hid[h], s);
    g_mod[b * Cc + o] = 1.f / (1.f + expf(-s));
}

// ---------------- FUSED: depthwise 3x3 + p1 GEMM(+ReLU) + folded p2 ----------------
// Thread = 4px x 16hid. ONE barrier per chunk; next-chunk cp.async issued AFTER
// the barrier so triple buffering is race-free (writer slot (c+2)%3 vs readers
// (c+1)%3 [stageB] and c%3 [stageC], all threads provably inside iter c body).
#define TW 32
#define TH 8
#define HALO 340   // 10*34
#define CHK 8
#define NCHUNK (C2 / CHK)
#define NSLOT 11   // ceil(CHK*HALO / 256)

struct __align__(16) SmemT {
    float tiles[3][CHK * HALO];     // triple-buffered halo tiles
    float xs[2][CHK][TW * TH];      // double-buffered dw output
    float wch[3][CHK * HID];        // triple-buffered p1 weights
    float wdw[3][CHK * 12];         // triple-buffered dw taps+bias (12-float rows)
};

__global__ __launch_bounds__(256, 2)
void dwgemm_kernel(const float* __restrict__ rgb, const float* __restrict__ tir,
                   const float* __restrict__ dww, const float* __restrict__ dwb,
                   const float* __restrict__ p1b) {
    __shared__ union {
        SmemT s;
        float4 red[4][TW * TH];
    } u;

    const int tid = threadIdx.x;
    const int tx0 = blockIdx.x * TW;
    const int ty0 = blockIdx.y * TH;
    const int b   = blockIdx.z;
    const int lx = tid & 31, ly = tid >> 5;
    const int hg = tid >> 6;        // hid group 0..3 (16 hid each)
    const int pg = tid & 63;        // pixels pg*4..pg*4+3

    // ---- chunk-invariant loader addressing ----
    int ofs[NSLOT];
    unsigned vmask = 0;
    #pragma unroll
    for (int sl = 0; sl < NSLOT; sl++) {
        int i = sl * 256 + tid;
        int ch = i / HALO;
        int rem = i - ch * HALO;
        int r = rem / 34, col = rem - r * 34;
        int gy = ty0 + r - 1, gx = tx0 + col - 1;
        bool have = (i < CHK * HALO);
        bool in = have && ((unsigned)gy < (unsigned)Hh) && ((unsigned)gx < (unsigned)Ww);
        ofs[sl] = (have ? ch * HW : 0) + (in ? gy * Ww + gx : 0);
        if (in) vmask |= 1u << sl;
    }

    const float* rbase = rgb + (size_t)b * Cc * HW;
    const float* tbase = tir + (size_t)b * Cc * HW;
    const uint32_t tiles_a = smem_u32(u.s.tiles);
    const uint32_t wch_a   = smem_u32(u.s.wch);
    const uint32_t wdw_a   = smem_u32(u.s.wdw);

    auto load_chunk = [&](int chunk, int bt) {
        const float* base = (chunk < 32 ? rbase : tbase) + (size_t)((chunk & 31) * CHK) * HW;
        uint32_t dst0 = tiles_a + (bt * (CHK * HALO) + tid) * 4;
        #pragma unroll
        for (int sl = 0; sl < NSLOT; sl++) {
            if (sl < NSLOT - 1 || tid < (CHK * HALO - (NSLOT - 1) * 256)) {
                int in = (vmask >> sl) & 1;
                cpa4(dst0 + sl * 256 * 4, base + ofs[sl], in ? 4 : 0);
            }
        }
        cpa4(wch_a + (bt * (CHK * HID) + tid) * 4,       g_p1wT + chunk * (CHK * HID) + tid, 4);
        cpa4(wch_a + (bt * (CHK * HID) + tid + 256) * 4, g_p1wT + chunk * (CHK * HID) + tid + 256, 4);
        if (tid < CHK * 12) {
            int cc = tid / 12, k = tid - cc * 12;
            const float* src = (k < 9) ? dww + (chunk * CHK + cc) * 9 + k
                                       : dwb + chunk * CHK + cc;
            cpa4(wdw_a + (bt * (CHK * 12) + tid) * 4, src, (k <= 9) ? 4 : 0);
        }
    };

    // stage B: depthwise for my pixel (lx,ly), chunk data in buffer bt -> xs[xb]
    auto stageB = [&](int bt, int xb) {
        const float* t0 = &u.s.tiles[bt][ly * 34 + lx];
        const float* wd = &u.s.wdw[bt][0];
        #pragma unroll
        for (int cc = 0; cc < CHK; cc++) {
            const float* t = t0 + cc * HALO;
            float4 wa = *(const float4*)(wd + cc * 12);
            float4 wb = *(const float4*)(wd + cc * 12 + 4);
            float2 wc = *(const float2*)(wd + cc * 12 + 8);
            float o = wc.y;   // bias
            o = fmaf(wa.x, t[0],  fmaf(wa.y, t[1],  fmaf(wa.z, t[2],
                fmaf(wa.w, t[34], fmaf(wb.x, t[35], fmaf(wb.y, t[36],
                fmaf(wb.z, t[68], fmaf(wb.w, t[69], fmaf(wc.x, t[70], o)))))))));
            u.s.xs[xb][cc][ly * TW + lx] = o;
        }
    };

    unsigned long long acc[32];
    #pragma unroll
    for (int i = 0; i < 32; i++) acc[i] = 0ULL;

    // prologue: chunks 0,1 in flight; stage B for chunk 0
    load_chunk(0, 0); cpa_commit();
    load_chunk(1, 1); cpa_commit();
    cpa_wait1();                 // chunk 0 resident
    __syncthreads();
    stageB(0, 0);

    for (int chunk = 0; chunk < NCHUNK; chunk++) {
        cpa_wait0();             // chunk+1 resident (only outstanding group)
        __syncthreads();         // all threads now inside this iteration's body

        // issue next-next chunk AFTER the barrier (race-free slot reuse)
        if (chunk + 2 < NCHUNK) { load_chunk(chunk + 2, (chunk + 2) % 3); cpa_commit(); }

        if (chunk + 1 < NCHUNK) stageB((chunk + 1) % 3, (chunk + 1) & 1);

        // ---- stage C: GEMM on xs[chunk&1] with wch[chunk%3] ----
        const float* wc0 = &u.s.wch[chunk % 3][hg * 16];
        const float* xsb = &u.s.xs[chunk & 1][0][0];
        #pragma unroll
        for (int cc = 0; cc < CHK; cc++) {
            float4 x4 = *(const float4*)(xsb + cc * (TW * TH) + pg * 4);
            const ulonglong2* wp = (const ulonglong2*)(wc0 + cc * HID);
            ulonglong2 q0 = wp[0], q1 = wp[1], q2 = wp[2], q3 = wp[3];
            unsigned long long w2[8] = {q0.x, q0.y, q1.x, q1.y, q2.x, q2.y, q3.x, q3.y};
            unsigned long long xx;
            xx = pk2(x4.x);
            #pragma unroll
            for (int k = 0; k < 8; k++) fma2(acc[0*8+k], w2[k], xx);
            xx = pk2(x4.y);
            #pragma unroll
            for (int k = 0; k < 8; k++) fma2(acc[1*8+k], w2[k], xx);
            xx = pk2(x4.z);
            #pragma unroll
            for (int k = 0; k < 8; k++) fma2(acc[2*8+k], w2[k], xx);
            xx = pk2(x4.w);
            #pragma unroll
            for (int k = 0; k < 8; k++) fma2(acc[3*8+k], w2[k], xx);
        }
    }

    // ---- Epilogue: bias + ReLU + folded p2 -> partial offsets ----
    float bl[16];
    #pragma unroll
    for (int k = 0; k < 16; k++) bl[k] = p1b[hg * 16 + k];
    float bo[4] = {g_p2beff[0], g_p2beff[1], g_p2beff[2], g_p2beff[3]};
    __syncthreads();   // done with SmemT; union red reuse

    #pragma unroll
    for (int j = 0; j < 4; j++) {
        float4 o = make_float4(0.f, 0.f, 0.f, 0.f);
        #pragma unroll
        for (int k = 0; k < 8; k++) {
            float h0, h1;
            upk2(h0, h1, acc[j * 8 + k]);
            h0 = fmaxf(h0 + bl[2 * k], 0.f);
            h1 = fmaxf(h1 + bl[2 * k + 1], 0.f);
            const float* p2 = g_p2eff + (hg * 16 + 2 * k) * 4;
            o.x += p2[0] * h0 + p2[4] * h1;
            o.y += p2[1] * h0 + p2[5] * h1;
            o.z += p2[2] * h0 + p2[6] * h1;
            o.w += p2[3] * h0 + p2[7] * h1;
        }
        u.red[hg][pg * 4 + j] = o;
    }
    __syncthreads();

    {
        float4 s0 = u.red[0][tid], s1 = u.red[1][tid], s2 = u.red[2][tid], s3 = u.red[3][tid];
        float4 s;
        s.x = s0.x + s1.x + s2.x + s3.x + bo[0];
        s.y = s0.y + s1.y + s2.y + s3.y + bo[1];
        s.z = s0.z + s1.z + s2.z + s3.z + bo[2];
        s.w = s0.w + s1.w + s2.w + s3.w + bo[3];
        int py = ty0 + (tid >> 5), px = tx0 + (tid & 31);
        ((float4*)g_off)[b * HW + py * Ww + px] = s;
    }
}

// ---------------- bilinear sample + mod + quality ----------------
__global__ void sample_kernel(const float* __restrict__ rgb, const float* __restrict__ tir,
                              float* __restrict__ out) {
    int x = threadIdx.x;        // 128
    int y = blockIdx.x;         // 128
    int b = blockIdx.y;         // 8
    __shared__ float smod[Cc];
    for (int i = threadIdx.x; i < Cc; i += 128) smod[i] = g_mod[b * Cc + i];
    __syncthreads();
    int hw = y * Ww + x;
    int p = b * HW + hw;
    float4 off = ((const float4*)g_off)[p];

    float ixr = fminf(fmaxf((float)x + off.x, 0.f), 127.f);
    float iyr = fminf(fmaxf((float)y + off.y, 0.f), 127.f);
    float ixt = fminf(fmaxf((float)x + off.z, 0.f), 127.f);
    float iyt = fminf(fmaxf((float)y + off.w, 0.f), 127.f);

    float fx0r = floorf(ixr), fy0r = floorf(iyr);
    int x0r = (int)fx0r, y0r = (int)fy0r;
    int x1r = min(x0r + 1, 127), y1r = min(y0r + 1, 127);
    float wxr = ixr - fx0r, wyr = iyr - fy0r;
    int i00r = y0r*Ww + x0r, i01r = y0r*Ww + x1r, i10r = y1r*Ww + x0r, i11r = y1r*Ww + x1r;

    float fx0t = floorf(ixt), fy0t = floorf(iyt);
    int x0t = (int)fx0t, y0t = (int)fy0t;
    int x1t = min(x0t + 1, 127), y1t = min(y0t + 1, 127);
    float wxt = ixt - fx0t, wyt = iyt - fy0t;
    int i00t = y0t*Ww + x0t, i01t = y0t*Ww + x1t, i10t = y1t*Ww + x0t, i11t = y1t*Ww + x1t;

    const float* rb = rgb + (size_t)b * Cc * HW;
    const float* tb = tir + (size_t)b * Cc * HW;
    float* outR = out + (size_t)b * Cc * HW + hw;
    float* outT = out + (size_t)Bn * Cc * HW + (size_t)b * Cc * HW + hw;

    float qacc = 0.f;
    #pragma unroll 4
    for (int c = 0; c < Cc; c++) {
        size_t co = (size_t)c * HW;
        float v00 = rb[co + i00r], v01 = rb[co + i01r];
        float v10 = rb[co + i10r], v11 = rb[co + i11r];
        float topr = v00 * (1.f - wxr) + v01 * wxr;
        float botr = v10 * (1.f - wxr) + v11 * wxr;
        float rv = (topr * (1.f - wyr) + botr * wyr) * smod[c];

        float u00 = tb[co + i00t], u01 = tb[co + i01t];
        float u10 = tb[co + i10t], u11 = tb[co + i11t];
        float topt = u00 * (1.f - wxt) + u01 * wxt;
        float bott = u10 * (1.f - wxt) + u11 * wxt;
        float tv = (topt * (1.f - wyt) + bott * wyt) * smod[c];

        outR[co] = rv;
        outT[co] = tv;
        qacc += fabsf(rv - tv);
    }
    float q = 1.f - qacc * (1.f / (float)Cc);
    out[(size_t)2 * Bn * Cc * HW + p] = 1.f / (1.f + expf(-q));
}

extern "C" void kernel_launch(void* const* d_in, const int* in_sizes, int n_in,
                              void* d_out, int out_size) {
    const float* rgb  = (const float*)d_in[0];
    const float* tir  = (const float*)d_in[1];
    const float* dw_w = (const float*)d_in[2];
    const float* dw_b = (const float*)d_in[3];
    const float* p1_w = (const float*)d_in[4];
    const float* p1_b = (const float*)d_in[5];
    const float* p2_w = (const float*)d_in[6];
    const float* p2_b = (const float*)d_in[7];
    const float* m1_w = (const float*)d_in[8];
    const float* m1_b = (const float*)d_in[9];
    const float* m2_w = (const float*)d_in[10];
    const float* m2_b = (const float*)d_in[11];
    float* out = (float*)d_out;

    prep_kernel<<<129, 256>>>(p1_w, p2_w, p2_b);
    gap_kernel<<<Bn * C2, 256>>>(rgb, tir);
    mod_kernel<<<Bn, 256>>>(m1_w, m1_b, m2_w, m2_b);
    dwgemm_kernel<<<dim3(Ww / TW, Hh / TH, Bn), 256>>>(rgb, tir, dw_w, dw_b, p1_b);
    sample_kernel<<<dim3(Hh, Bn), Ww>>>(rgb, tir, out);
}